// round 15
// baseline (speedup 1.0000x reference)
#include <cuda_runtime.h>
#include <math.h>

// F0Resonance: out[b,e,s] = normalize_s( sum_o w_o * sin(phase_o[s]) )
//
// Numerics model H4 (VALIDATED, rel_err 2.3489e-7): cumsum -> reduce_window;
// XLA ReduceWindowRewriter (base_length=16) recursion 32768 -> 2048 -> 128 -> 8.
// For 0-based sample s, g=s>>4, r=s&15:
//   phase(s) = fl(EB(g) + LA[r]);  EB(g) = 0 if g==0 else fl(ECt[(g-1)>>4] + LB[(g-1)&15])
// Octave-axis cumsums (N=16): naive sequential folds. theta: separate mul/add.
// The PHASE rounding chain is bit-matched to the reference — do not alter it.
//
// R14 structure: setup1 (per-ev scan tables) -> setup2 (full EB[ev][o][g] table,
// 32 MB scratch) -> main (1 LDS + 6 FMA-pipe ops per sample-octave, fused
// last-block normalization via atomicMax + counter; norm kernel eliminated).

#define NSAMP  32768
#define NOCT   16
#define NEV    256            // B*E = 4*64
#define K1T    512            // 16 warps; each warp owns 256 samples
#define QY     8              // 8 * 16 warps * 256 samples = 32768
#define NGRP   2048           // NSAMP / 16
#define GPB    256            // groups per main block

// per-ev tables from setup1: LA[16][16], LB[16][16], ECt[16][128], w[16]
#define TAB_LA   0
#define TAB_LB   256
#define TAB_ECT  512
#define TAB_W    2560
#define TAB_SZ   2576
__device__ float g_tab[NEV * TAB_SZ];
__device__ float g_ebt[NEV * NOCT * NGRP];       // 32 MB EB table
__device__ unsigned g_pmax[NEV];                 // float-as-uint max (>=0)
__device__ unsigned g_cnt[NEV];                  // arrival counters

__global__ void __launch_bounds__(16)
f0res_setup1(const float* __restrict__ f0_in,
             const float* __restrict__ dc_in,
             const float* __restrict__ fs_in) {
    const int ev = blockIdx.x;
    const int o  = threadIdx.x;          // 0..15
    const int n  = o + 1;
    float* tab = g_tab + ev * TAB_SZ;

    const float MIN_FREQ_F   = (float)(20.0 / 11025.0);
    const float FREQ_RANGE_F = (float)(3000.0 / 11025.0 - 20.0 / 11025.0);
    const float PI_F = 3.14159265358979323846f;

    float f0 = fabsf(f0_in[ev]);
    float f0a = __fmul_rn(__fadd_rn(MIN_FREQ_F, __fmul_rn(f0, FREQ_RANGE_F)), PI_F);

    float fs = fs_in[ev];
    float fac = fs;
    for (int i = 1; i < n; i++) fac = __fadd_rn(fac, fs);
    const float th = __fmul_rn(f0a, fac);

    float dc = dc_in[ev];
    float s1 = 1.0f / (1.0f + expf(-dc));
    float s2 = 1.0f / (1.0f + expf(-s1));
    float decay = __fadd_rn(0.01f, __fmul_rn(s2, (float)((1.0 - 0.01) * 0.95)));
    float ld = logf(__fadd_rn(decay, 1e-12f));
    float cum = ld;
    for (int i = 1; i < n; i++) cum = __fadd_rn(cum, ld);
    tab[TAB_W + o] = expf(cum);

    float LA[16], LB[16], LC[16], SD[8];
    float acc = 0.f;
    for (int r = 0; r < 16; r++) { acc = __fadd_rn(acc, th); LA[r] = acc; }
    const float TA = acc;
    acc = 0.f;
    for (int r = 0; r < 16; r++) { acc = __fadd_rn(acc, TA); LB[r] = acc; }
    const float TB = acc;
    acc = 0.f;
    for (int r = 0; r < 16; r++) { acc = __fadd_rn(acc, TB); LC[r] = acc; }
    const float TC = acc;
    acc = 0.f;
    for (int j = 0; j < 8; j++) { acc = __fadd_rn(acc, TC); SD[j] = acc; }

    for (int r = 0; r < 16; r++) {
        tab[TAB_LA + o * 16 + r] = LA[r];
        tab[TAB_LB + o * 16 + r] = LB[r];
    }
    tab[TAB_ECT + o * 128 + 0] = 0.f;
    for (int m = 0; m < 127; m++) {
        const int i3 = m >> 4, r3 = m & 15;
        float ED = (i3 == 0) ? 0.f : SD[i3 - 1];
        tab[TAB_ECT + o * 128 + m + 1] = __fadd_rn(ED, LC[r3]);
    }
}

// Expand EB(g) = fl(ECt[(g-1)>>4] + LB[(g-1)&15]) (0 for g==0) for all g.
__global__ void __launch_bounds__(256)
f0res_setup2() {
    const int ev = blockIdx.x;
    const int o  = blockIdx.y;
    const int tid = threadIdx.x;
    __shared__ float sLB[16];
    __shared__ float sECt[128];
    const float* tab = g_tab + ev * TAB_SZ;
    if (tid < 16)  sLB[tid]  = tab[TAB_LB + o * 16 + tid];
    if (tid < 128) sECt[tid] = tab[TAB_ECT + o * 128 + tid];
    __syncthreads();
    float* dst = g_ebt + ((ev * NOCT + o) << 11);
#pragma unroll
    for (int i = 0; i < NGRP / 256; i++) {
        const int g = i * 256 + tid;
        float v = 0.f;
        if (g > 0) {
            const int m = g - 1;
            v = __fadd_rn(sECt[m >> 4], sLB[m & 15]);
        }
        dst[g] = v;
    }
}

__global__ void __launch_bounds__(K1T, 4)
f0res_main(float* __restrict__ out) {
    const int ev   = blockIdx.x;          // 0..255
    const int q    = blockIdx.y;          // 0..7
    const int tid  = threadIdx.x;
    const int warp = tid >> 5;
    const int lane = tid & 31;

    __shared__ float sh_EB[NOCT * GPB];   // EB for this block's 256 groups
    __shared__ float sh_LA[256];
    __shared__ float sh_w[NOCT];
    __shared__ float sh_wmax[K1T / 32];
    __shared__ float sh_denom;
    __shared__ int   sh_islast;

    // ---- Prolog: coalesced copy of EB slice (16 KB) + LA + w ----
    {
        const int ebase = ev * NOCT;
#pragma unroll
        for (int i = tid; i < NOCT * GPB / 4; i += K1T) {
            const int o = i >> 6;                       // 64 float4 per octave
            const int f = i & 63;
            const float4* src4 =
                (const float4*)(g_ebt + ((ebase + o) << 11) + q * GPB);
            ((float4*)(sh_EB + o * GPB))[f] = src4[f];
        }
        if (tid < 256) sh_LA[tid] = g_tab[ev * TAB_SZ + TAB_LA + tid];
        if (tid < NOCT) sh_w[tid] = g_tab[ev * TAB_SZ + TAB_W + tid];
    }
    __syncthreads();

    // ---- Main: warp W owns samples [W*256, W*256+256) globally ----
    // lane l: s = W*256 + j*32 + l  =>  r = l&15 fixed, local group = warp*16+j*2+half
    const int r     = lane & 15;
    const int half  = lane >> 4;
    const int gbase = warp * 16 + half;   // + 2j at compile time

    const float T1 = 6.2831854820251464844f;        // fl(2*pi)
    const float T2 = -1.7484556000744487988e-7f;    // fl(2*pi - T1)
    const float INV_2PI = 0.15915493667125701904f;

    float acc[8];
#pragma unroll
    for (int j = 0; j < 8; j++) acc[j] = 0.f;

#pragma unroll
    for (int o = 0; o < NOCT; o++) {
        const float lav = sh_LA[o * 16 + r];   // broadcast-dedup, conflict-free
        const float wv  = sh_w[o];
#pragma unroll
        for (int j = 0; j < 8; j++) {
            float EB = sh_EB[o * GPB + gbase + 2 * j];  // imm-offset LDS, bcast
            float p  = __fadd_rn(EB, lav);              // fl(EB + LA[r]) EXACT
            // 2-term Cody-Waite (residual ~1e-9 rad at |p|<5e5) + MUFU sin
            float kf = rintf(__fmul_rn(p, INV_2PI));
            float rr = fmaf(kf, -T1, p);
            rr = fmaf(kf, -T2, rr);
            float sv = __sinf(rr);
            acc[j] = fmaf(sv, wv, acc[j]);              // amplitude path: FMA ok
        }
    }

    // ---- Store raw osc (coalesced) + per-thread max ----
    float* op = out + (size_t)ev * NSAMP + (q * 16 + warp) * 256;
    float mx = 0.f;
#pragma unroll
    for (int j = 0; j < 8; j++) {
        op[j * 32 + lane] = acc[j];
        mx = fmaxf(mx, fabsf(acc[j]));
    }

    // ---- Block max -> global atomic max; last block normalizes ----
#pragma unroll
    for (int off = 16; off; off >>= 1)
        mx = fmaxf(mx, __shfl_xor_sync(0xffffffffu, mx, off));
    if (lane == 0) sh_wmax[warp] = mx;
    __syncthreads();
    if (tid == 0) {
        float bm = sh_wmax[0];
#pragma unroll
        for (int i = 1; i < K1T / 32; i++) bm = fmaxf(bm, sh_wmax[i]);
        atomicMax(&g_pmax[ev], __float_as_uint(bm));   // bm >= 0: order-safe
        __threadfence();
        unsigned old = atomicAdd(&g_cnt[ev], 1u);
        sh_islast = (old == QY - 1);
    }
    __syncthreads();

    if (sh_islast) {
        if (tid == 0) {
            unsigned um = atomicMax(&g_pmax[ev], 0u);  // atomic read of max
            sh_denom = __fadd_rn(__uint_as_float(um), 1e-8f);
            g_pmax[ev] = 0u;                           // reset for next replay
            g_cnt[ev]  = 0u;
        }
        __syncthreads();
        const float denom = sh_denom;
        float4* p4 = (float4*)(out + (size_t)ev * NSAMP);
#pragma unroll
        for (int i = 0; i < (NSAMP / 4) / K1T; i++) {
            const int k = tid + i * K1T;
            float4 v = p4[k];                          // L2-hot re-read
            v.x = v.x / denom;
            v.y = v.y / denom;
            v.z = v.z / denom;
            v.w = v.w / denom;
            p4[k] = v;
        }
    }
}

extern "C" void kernel_launch(void* const* d_in, const int* in_sizes, int n_in,
                              void* d_out, int out_size) {
    const float* f0 = (const float*)d_in[0];
    const float* dc = (const float*)d_in[1];
    // d_in[2] = phase_offsets: computed but unused by the reference
    const float* fs = (const float*)d_in[3];
    f0res_setup1<<<NEV, 16>>>(f0, dc, fs);
    f0res_setup2<<<dim3(NEV, NOCT), 256>>>();
    f0res_main<<<dim3(NEV, QY), K1T>>>((float*)d_out);
}